// round 1
// baseline (speedup 1.0000x reference)
#include <cuda_runtime.h>
#include <cstddef>

// Problem constants (fixed shapes for this problem)
#define BB 256      // batch
#define TT 2048     // time steps
#define HH 64       // hidden
#define GG 256      // 4*H gates

typedef unsigned long long u64;

// ---------------- packed f32x2 helpers (sm_100+) ----------------
__device__ __forceinline__ u64 fma2(u64 a, u64 b, u64 c) {
    u64 d;
    asm("fma.rn.f32x2 %0, %1, %2, %3;" : "=l"(d) : "l"(a), "l"(b), "l"(c));
    return d;
}
__device__ __forceinline__ u64 add2(u64 a, u64 b) {
    u64 d;
    asm("add.rn.f32x2 %0, %1, %2;" : "=l"(d) : "l"(a), "l"(b));
    return d;
}
__device__ __forceinline__ float hsum2(u64 a) {
    float lo = __uint_as_float((unsigned)(a & 0xffffffffull));
    float hi = __uint_as_float((unsigned)(a >> 32));
    return lo + hi;
}

// fast sigmoid / tanh via MUFU ex2 + rcp (≈2 ulp, saturates correctly at ±inf)
__device__ __forceinline__ float fsigmoid(float x) {
    float e = __expf(-x);
    return __fdividef(1.0f, 1.0f + e);
}
__device__ __forceinline__ float ftanh(float x) {
    float e = __expf(2.0f * x);
    return 1.0f - __fdividef(2.0f, e + 1.0f);
}

// ---------------- device scratch (no cudaMalloc allowed) ----------------
__device__ float g_y0[(size_t)BB * TT * HH];    // 128 MB, layer0 hidden outputs
__device__ float g_xp1[(size_t)BB * TT * GG];   // 512 MB, layer1 input projections
__device__ float g_y1[(size_t)BB * TT * HH];    // 128 MB, layer1 hidden outputs

// ---------------- LSTM recurrence kernel ----------------
// One CTA per batch row. 256 threads: thread g owns gate row g of Whh
// (64 weights in registers, packed f32x2). Threads 0..63 additionally own
// the cell state c[j] in a register and perform the elementwise update.
// Gate order (PyTorch/JAX): rows [0:64)=i, [64:128)=f, [128:192)=g, [192:256)=o.
template <int LAYER>
__global__ __launch_bounds__(256, 2) void lstm_recur_kernel(
    const float* __restrict__ x,     // LAYER==0: input [B,T]  (unused for LAYER==1)
    const float* __restrict__ Wih,   // LAYER==0: [256,1]      (unused for LAYER==1)
    const float* __restrict__ Whh,   // [256,64] row-major
    const float* __restrict__ bih,
    const float* __restrict__ bhh,
    const float* __restrict__ h0,    // [B,64] for this layer
    const float* __restrict__ c0)    // [B,64] for this layer
{
    __shared__ __align__(16) float h_sh[HH];
    __shared__ float gate_sh[GG];

    const int g = threadIdx.x;
    const int b = blockIdx.x;

    // ---- load this gate's Whh row into registers (packed pairs) ----
    u64 w[32];
    {
        const ulonglong2* wr = (const ulonglong2*)(Whh + (size_t)g * HH);
#pragma unroll
        for (int i = 0; i < 16; i++) {
            ulonglong2 v = wr[i];
            w[2 * i]     = v.x;
            w[2 * i + 1] = v.y;
        }
    }
    const float bias = bih[g] + bhh[g];
    const float wih0 = (LAYER == 0) ? Wih[g] : 0.0f;
    const int gate_kind = g >> 6;  // 0:i 1:f 2:g 3:o

    float c = 0.0f;
    if (g < HH) {
        h_sh[g] = h0[(size_t)b * HH + g];
        c       = c0[(size_t)b * HH + g];
    }
    __syncthreads();

    const size_t xbase0 = (size_t)b * TT;               // layer0: x[b][t]
    const size_t xbase1 = (size_t)b * TT * GG + g;      // layer1: xp1[(b,t)][g]
    float* yout = (LAYER == 0) ? g_y0 : g_y1;
    const size_t ybase = (size_t)b * TT * HH;

    // prefetch first input term
    float xin;
    if (LAYER == 0) xin = __ldg(x + xbase0);
    else            xin = __ldg(g_xp1 + xbase1);

#pragma unroll 1
    for (int t = 0; t < TT; t++) {
        // prefetch next step's input (hidden behind the FMA phase)
        const int tn = (t + 1 < TT) ? (t + 1) : t;
        float xnext;
        if (LAYER == 0) xnext = __ldg(x + xbase0 + tn);
        else            xnext = __ldg(g_xp1 + xbase1 + (size_t)tn * GG);

        // ---- phase 1: gate pre-activation = bias + xp + Whh[g,:]·h ----
        u64 a0 = 0ull, a1 = 0ull, a2 = 0ull, a3 = 0ull;
        const ulonglong2* hs = (const ulonglong2*)h_sh;
#pragma unroll
        for (int i = 0; i < 8; i++) {
            ulonglong2 h1 = hs[2 * i];
            ulonglong2 h2 = hs[2 * i + 1];
            a0 = fma2(w[4 * i + 0], h1.x, a0);
            a1 = fma2(w[4 * i + 1], h1.y, a1);
            a2 = fma2(w[4 * i + 2], h2.x, a2);
            a3 = fma2(w[4 * i + 3], h2.y, a3);
        }
        a0 = add2(a0, a1);
        a2 = add2(a2, a3);
        a0 = add2(a0, a2);
        float pre = bias + hsum2(a0);
        if (LAYER == 0) pre += xin * wih0;
        else            pre += xin;

        // own-gate nonlinearity (spreads MUFU over all 256 threads)
        float act = (gate_kind == 2) ? ftanh(pre) : fsigmoid(pre);
        gate_sh[g] = act;
        xin = xnext;
        __syncthreads();   // gates ready; all h_sh reads of this step done

        // ---- phase 2: cell/hidden update by unit threads ----
        if (g < HH) {
            float gi = gate_sh[g];
            float gf = gate_sh[g + 64];
            float gg = gate_sh[g + 128];
            float go = gate_sh[g + 192];
            c = gf * c + gi * gg;
            float hv = go * ftanh(c);
            h_sh[g] = hv;
            yout[ybase + (size_t)t * HH + g] = hv;
        }
        __syncthreads();   // h ready for next step
    }
}

// ---------------- K2: xp1 = y0 @ Wih1^T  ([B*T,64] x [64,256] -> [B*T,256]) ----------------
// Block: 256 threads (one per gate), each holds its Wih1 row in registers.
// Each block processes 64 rows of y0 staged through shared memory.
#define K2_ROWS 64
__global__ __launch_bounds__(256, 2) void xp_gemm_kernel(const float* __restrict__ Wih1)
{
    __shared__ __align__(16) float ys[K2_ROWS * HH];
    const int g = threadIdx.x;

    u64 w[32];
    {
        const ulonglong2* wr = (const ulonglong2*)(Wih1 + (size_t)g * HH);
#pragma unroll
        for (int i = 0; i < 16; i++) {
            ulonglong2 v = wr[i];
            w[2 * i]     = v.x;
            w[2 * i + 1] = v.y;
        }
    }

    const size_t r0 = (size_t)blockIdx.x * K2_ROWS;
    // cooperative load of 64 rows x 64 floats = 1024 float4
    {
        const float4* src = (const float4*)(g_y0 + r0 * HH);
        float4* dst = (float4*)ys;
#pragma unroll
        for (int i = 0; i < 4; i++) dst[g + i * 256] = src[g + i * 256];
    }
    __syncthreads();

#pragma unroll 1
    for (int r = 0; r < K2_ROWS; r++) {
        const ulonglong2* hs = (const ulonglong2*)(ys + r * HH);
        u64 a0 = 0ull, a1 = 0ull, a2 = 0ull, a3 = 0ull;
#pragma unroll
        for (int i = 0; i < 8; i++) {
            ulonglong2 h1 = hs[2 * i];
            ulonglong2 h2 = hs[2 * i + 1];
            a0 = fma2(w[4 * i + 0], h1.x, a0);
            a1 = fma2(w[4 * i + 1], h1.y, a1);
            a2 = fma2(w[4 * i + 2], h2.x, a2);
            a3 = fma2(w[4 * i + 3], h2.y, a3);
        }
        a0 = add2(a0, a1);
        a2 = add2(a2, a3);
        a0 = add2(a0, a2);
        g_xp1[(r0 + r) * GG + g] = hsum2(a0);
    }
}

// ---------------- K4: pred = y1 @ Wlin^T + blin ----------------
__global__ __launch_bounds__(256) void out_kernel(
    const float* __restrict__ Wlin,
    const float* __restrict__ blin,
    float* __restrict__ out)
{
    __shared__ __align__(16) float wl[HH];
    const int tid = threadIdx.x;
    if (tid < HH) wl[tid] = Wlin[tid];
    __syncthreads();

    const size_t idx = (size_t)blockIdx.x * 256 + tid;
    const ulonglong2* row = (const ulonglong2*)(g_y1 + idx * HH);
    const ulonglong2* wv  = (const ulonglong2*)wl;
    u64 a0 = 0ull, a1 = 0ull, a2 = 0ull, a3 = 0ull;
#pragma unroll
    for (int i = 0; i < 8; i++) {
        ulonglong2 h1 = row[2 * i];
        ulonglong2 w1 = wv[2 * i];
        ulonglong2 h2 = row[2 * i + 1];
        ulonglong2 w2 = wv[2 * i + 1];
        a0 = fma2(w1.x, h1.x, a0);
        a1 = fma2(w1.y, h1.y, a1);
        a2 = fma2(w2.x, h2.x, a2);
        a3 = fma2(w2.y, h2.y, a3);
    }
    a0 = add2(a0, a1);
    a2 = add2(a2, a3);
    a0 = add2(a0, a2);
    out[idx] = hsum2(a0) + __ldg(blin);
}

// ---------------- launch ----------------
extern "C" void kernel_launch(void* const* d_in, const int* in_sizes, int n_in,
                              void* d_out, int out_size)
{
    const float* input = (const float*)d_in[0];   // [B,T]
    const float* h0    = (const float*)d_in[1];   // [2,B,H]
    const float* c0    = (const float*)d_in[2];   // [2,B,H]
    const float* Wih0  = (const float*)d_in[3];   // [256,1]
    const float* Whh0  = (const float*)d_in[4];   // [256,64]
    const float* bih0  = (const float*)d_in[5];
    const float* bhh0  = (const float*)d_in[6];
    const float* Wih1  = (const float*)d_in[7];   // [256,64]
    const float* Whh1  = (const float*)d_in[8];   // [256,64]
    const float* bih1  = (const float*)d_in[9];
    const float* bhh1  = (const float*)d_in[10];
    const float* Wlin  = (const float*)d_in[11];  // [1,64]
    const float* blin  = (const float*)d_in[12];  // [1]
    float* out = (float*)d_out;                   // [B,T]

    (void)in_sizes; (void)n_in; (void)out_size;

    // Layer 0 recurrence -> g_y0
    lstm_recur_kernel<0><<<BB, 256>>>(input, Wih0, Whh0, bih0, bhh0,
                                      h0, c0);
    // xp1 = y0 @ Wih1^T  -> g_xp1
    xp_gemm_kernel<<<(BB * TT) / K2_ROWS, 256>>>(Wih1);
    // Layer 1 recurrence -> g_y1
    lstm_recur_kernel<1><<<BB, 256>>>(input /*unused*/, Wih1 /*unused*/, Whh1,
                                      bih1, bhh1,
                                      h0 + (size_t)BB * HH, c0 + (size_t)BB * HH);
    // pred = y1 @ Wlin^T + blin
    out_kernel<<<(BB * TT) / 256, 256>>>(Wlin, blin, out);
}